// round 14
// baseline (speedup 1.0000x reference)
#include <cuda_runtime.h>
#include <cuda_bf16.h>
#include <cstdint>

#define BB   4
#define NN   1024
#define TT   16
#define FINN 32
#define HH   128
#define LHID 64
#define NP   64
#define MTOT (NP * NN)

// ---------------- scratch ----------------
__device__ __nv_bfloat16 d_Whb[MTOT * HH];        // bf16 Wh (GEMM epilogue output, row-major)
__device__ __nv_bfloat16 d_h1b[MTOT * HH];        // bf16 layer-1 output [p][n][h]
__device__ __nv_bfloat16 d_gb [MTOT * HH];        // bf16 layer-2 output [p][n][h]
__device__ __nv_bfloat16 d_evb [MTOT];
__device__ __nv_bfloat16 d_ev2b[MTOT];
__device__ float         d_r  [MTOT];             // e^{-0.8 s_src}
__device__ unsigned      d_adjp[BB * NN * (NN / 32)];
__device__ __nv_bfloat16 d_XGb[MTOT * 256];       // bf16 input gates (bias included)
__device__ __nv_bfloat16 d_W2b [HH * HH];         // W2 transposed -> [n][k] bf16
__device__ __nv_bfloat16 d_Wihb[256 * HH];        // Wih [gate][k] bf16

// ---------------- helpers ----------------
__device__ __forceinline__ float sigf(float x)   { return 1.f / (1.f + __expf(-x)); }
__device__ __forceinline__ float tanhf_(float x) { return 1.f - 2.f / (__expf(2.f * x) + 1.f); }
__device__ __forceinline__ void mma_tf32(float* c, const unsigned* a, const unsigned* b) {
    asm volatile("mma.sync.aligned.m16n8k8.row.col.f32.tf32.tf32.f32 "
                 "{%0,%1,%2,%3}, {%4,%5,%6,%7}, {%8,%9}, {%0,%1,%2,%3};"
                 : "+f"(c[0]), "+f"(c[1]), "+f"(c[2]), "+f"(c[3])
                 : "r"(a[0]), "r"(a[1]), "r"(a[2]), "r"(a[3]), "r"(b[0]), "r"(b[1]));
}
__device__ __forceinline__ void mma_bf16(float* c, const unsigned* a, const unsigned* b) {
    asm volatile("mma.sync.aligned.m16n8k16.row.col.f32.bf16.bf16.f32 "
                 "{%0,%1,%2,%3}, {%4,%5,%6,%7}, {%8,%9}, {%0,%1,%2,%3};"
                 : "+f"(c[0]), "+f"(c[1]), "+f"(c[2]), "+f"(c[3])
                 : "r"(a[0]), "r"(a[1]), "r"(a[2]), "r"(a[3]), "r"(b[0]), "r"(b[1]));
}
__device__ __forceinline__ void ldm_x4(unsigned& r0, unsigned& r1, unsigned& r2, unsigned& r3,
                                       unsigned saddr) {
    asm volatile("ldmatrix.sync.aligned.m8n8.x4.shared.b16 {%0,%1,%2,%3}, [%4];"
                 : "=r"(r0), "=r"(r1), "=r"(r2), "=r"(r3) : "r"(saddr));
}
__device__ __forceinline__ void ldm_x4_trans(unsigned& r0, unsigned& r1, unsigned& r2, unsigned& r3,
                                             unsigned saddr) {
    asm volatile("ldmatrix.sync.aligned.m8n8.x4.trans.shared.b16 {%0,%1,%2,%3}, [%4];"
                 : "=r"(r0), "=r"(r1), "=r"(r2), "=r"(r3) : "r"(saddr));
}
__device__ __forceinline__ void cpasync16(unsigned saddr, const void* g) {
    asm volatile("cp.async.ca.shared.global [%0], [%1], 16;" :: "r"(saddr), "l"(g));
}
__device__ __forceinline__ void cpcommit() { asm volatile("cp.async.commit_group;"); }
__device__ __forceinline__ float elu2(float v) {
    v = v > 0.f ? v : __expf(v) - 1.f;
    v = v > 0.f ? v : __expf(v) - 1.f;
    return v;
}
__device__ __forceinline__ unsigned packbf(float a, float b) {
    __nv_bfloat162 p = __floats2bfloat162_rn(a, b);
    return *(unsigned*)&p;
}
__device__ __forceinline__ unsigned bfu(__nv_bfloat162 v) { return *(unsigned*)&v; }
__device__ __forceinline__ unsigned mask2(unsigned aw, int j0) {
    unsigned m = 0;
    if ((aw >> j0) & 1u)       m |= 0x0000FFFFu;
    if ((aw >> (j0 + 1)) & 1u) m |= 0xFFFF0000u;
    return m;
}

// ---------------- 1. prep: pack adjacency + bf16 weights (one launch) ----------------
__global__ void prep_all(const int* __restrict__ adj,
                         const float* __restrict__ W2, const float* __restrict__ Wih) {
    int idx = blockIdx.x * blockDim.x + threadIdx.x;
    if (idx < BB * NN * (NN / 32)) {
        long base = (long)idx * 32;
        unsigned bits = 0;
#pragma unroll
        for (int j = 0; j < 32; j++) bits |= (adj[base + j] > 0 ? 1u : 0u) << j;
        d_adjp[idx] = bits;
    }
    if (idx < HH * HH) {
        int n = idx >> 7, k = idx & 127;
        d_W2b[idx] = __float2bfloat16(W2[k * HH + n]);
    }
    if (idx < 256 * HH)
        d_Wihb[idx] = __float2bfloat16(Wih[idx]);
}

// ---------------- 2a. tf32 GEMM (layer 1: x gathered, K=32) -> d_Whb + scores ----
__global__ void __launch_bounds__(256, 2) gemm_l1(const float* __restrict__ A,
                                                  const float* __restrict__ Bw,
                                                  const float* __restrict__ avec) {
    int m0 = blockIdx.x * 128;
    int tid = threadIdx.x, lane = tid & 31, wid = tid >> 5;
    int wm = wid >> 2, wn = wid & 3;
    int g = lane >> 2, t = lane & 3;

    extern __shared__ float gsm[];
    float* As = gsm;             // [128][36]
    float* Bs = gsm + 4608;      // [32][136]
    __shared__ float sA[256];
    __shared__ float red[4][128][2];

    sA[tid] = avec[tid];

    float acc[4][4][4] = {};
    {
        int r = tid >> 1, k0 = (tid & 1) * 16;
        int m = m0 + r;
        int n = m & (NN - 1);
        int pp = m >> 10, tt2 = pp & 15, bb2 = pp >> 4;
        long base = (((long)(bb2 * NN + n) * TT + tt2) * FINN) + k0;
        unsigned dst = (unsigned)__cvta_generic_to_shared(&As[r * 36 + k0]);
#pragma unroll
        for (int q = 0; q < 4; q++) cpasync16(dst + q * 16, A + base + q * 4);
    }
    {
        int kr = tid >> 3, cq = tid & 7;
        const float* src = Bw + (long)kr * HH + cq * 16;
        unsigned dst = (unsigned)__cvta_generic_to_shared(&Bs[kr * 136 + cq * 16]);
#pragma unroll
        for (int q = 0; q < 4; q++) cpasync16(dst + q * 16, src + q * 4);
    }
    cpcommit();
    asm volatile("cp.async.wait_group 0;" ::: "memory");
    __syncthreads();

#pragma unroll
    for (int ks = 0; ks < 4; ks++) {
        unsigned a[4][4], bf[4][2];
#pragma unroll
        for (int mf = 0; mf < 4; mf++) {
            int r = wm * 64 + mf * 16 + g;
            a[mf][0] = __float_as_uint(As[r * 36 + ks * 8 + t]);
            a[mf][1] = __float_as_uint(As[(r + 8) * 36 + ks * 8 + t]);
            a[mf][2] = __float_as_uint(As[r * 36 + ks * 8 + t + 4]);
            a[mf][3] = __float_as_uint(As[(r + 8) * 36 + ks * 8 + t + 4]);
        }
#pragma unroll
        for (int nf = 0; nf < 4; nf++) {
            int cc = wn * 32 + nf * 8 + g;
            bf[nf][0] = __float_as_uint(Bs[(ks * 8 + t) * 136 + cc]);
            bf[nf][1] = __float_as_uint(Bs[(ks * 8 + t + 4) * 136 + cc]);
        }
#pragma unroll
        for (int mf = 0; mf < 4; mf++)
#pragma unroll
            for (int nf = 0; nf < 4; nf++)
                mma_tf32(acc[mf][nf], a[mf], bf[nf]);
    }

    // store bf16 Wh + fused scores
#pragma unroll
    for (int mf = 0; mf < 4; mf++) {
        int r = m0 + wm * 64 + mf * 16 + g;
#pragma unroll
        for (int nf = 0; nf < 4; nf++) {
            int cc = wn * 32 + nf * 8 + 2 * t;
            *(unsigned*)&d_Whb[(long)r * HH + cc] = packbf(acc[mf][nf][0], acc[mf][nf][1]);
            *(unsigned*)&d_Whb[(long)(r + 8) * HH + cc] = packbf(acc[mf][nf][2], acc[mf][nf][3]);
        }
    }
#pragma unroll
    for (int mf = 0; mf < 4; mf++) {
        float ps0 = 0.f, pd0 = 0.f, ps1 = 0.f, pd1 = 0.f;
#pragma unroll
        for (int nf = 0; nf < 4; nf++) {
            int cc = wn * 32 + nf * 8 + 2 * t;
#pragma unroll
            for (int dd = 0; dd < 2; dd++) {
                float a_s = sA[cc + dd], a_d = sA[128 + cc + dd];
                ps0 += acc[mf][nf][dd]     * a_s;
                pd0 += acc[mf][nf][dd]     * a_d;
                ps1 += acc[mf][nf][2 + dd] * a_s;
                pd1 += acc[mf][nf][2 + dd] * a_d;
            }
        }
#pragma unroll
        for (int o = 1; o <= 2; o <<= 1) {
            ps0 += __shfl_xor_sync(~0u, ps0, o);
            pd0 += __shfl_xor_sync(~0u, pd0, o);
            ps1 += __shfl_xor_sync(~0u, ps1, o);
            pd1 += __shfl_xor_sync(~0u, pd1, o);
        }
        if (t == 0) {
            int r = wm * 64 + mf * 16 + g;
            red[wn][r][0] = ps0;     red[wn][r][1] = pd0;
            red[wn][r + 8][0] = ps1; red[wn][r + 8][1] = pd1;
        }
    }
    __syncthreads();
    if (tid < 128) {
        float ss = red[0][tid][0] + red[1][tid][0] + red[2][tid][0] + red[3][tid][0];
        float sd = red[0][tid][1] + red[1][tid][1] + red[2][tid][1] + red[3][tid][1];
        long m = m0 + tid;
        d_evb [m] = __float2bfloat16(__expf(sd));
        d_ev2b[m] = __float2bfloat16(__expf(0.2f * sd));
        d_r   [m] = __expf(-0.8f * ss);
    }
}

// ---------------- 2b. bf16 GEMM (K=128) ----------------
// AMODE 0: A dense rows [m][128];  AMODE 1: A = d_gb gathered via (b,t,n) for xg
// SFUSE 1: bf16 out -> d_Whb + fused scores (layer 2; NTOT=128, gridDim.y=1)
// SFUSE 0: bf16 out + bias -> d_XGb (xg; NTOT=256)
template <int BIAS, int NTOT, int SFUSE, int AMODE>
__global__ void __launch_bounds__(256, 2) gemm_bf(const __nv_bfloat16* __restrict__ A,
                                                  const __nv_bfloat16* __restrict__ Bw,
                                                  const float* __restrict__ bi1,
                                                  const float* __restrict__ bi2,
                                                  const float* __restrict__ avec) {
    int m0 = blockIdx.x * 128;
    int c0 = blockIdx.y * 128;
    int tid = threadIdx.x, lane = tid & 31, wid = tid >> 5;
    int wm = wid >> 2, wn = wid & 3;
    int g = lane >> 2, t = lane & 3;

    extern __shared__ __nv_bfloat16 bsm[];
    unsigned asmem = (unsigned)__cvta_generic_to_shared(&bsm[0]);
    unsigned bsmem = asmem + 128 * 272;
    __shared__ float sA[SFUSE ? 256 : 1];
    __shared__ float red[SFUSE ? 4 : 1][SFUSE ? 128 : 1][2];

    if (SFUSE) sA[tid] = avec[tid];

    {
        int r = tid >> 1, h = (tid & 1) * 8;
        long arow;
        if (AMODE == 0) {
            arow = (long)(m0 + r) * HH;
        } else {
            int m = m0 + r;
            int tt2 = m & 15, bn = m >> 4;
            int n = bn & (NN - 1), b = bn >> 10;
            arow = ((long)(b * TT + tt2) * NN + n) * HH;   // d_gb [p][n][h]
        }
        const __nv_bfloat16* asrc = A + arow + h * 8;
        const __nv_bfloat16* bsrc = Bw + (long)(c0 + r) * HH + h * 8;
        unsigned adst = asmem + r * 272 + h * 16;
        unsigned bdst = bsmem + r * 272 + h * 16;
#pragma unroll
        for (int q = 0; q < 8; q++) {
            cpasync16(adst + q * 16, asrc + q * 8);
            cpasync16(bdst + q * 16, bsrc + q * 8);
        }
    }
    cpcommit();

    int mrow = lane & 7, msel = lane >> 3;
    unsigned aLane = asmem + ((msel & 1) * 8 + mrow) * 272 + (msel >> 1) * 16 + (wm * 64) * 272;
    unsigned bLane = bsmem + ((msel >> 1) * 8 + mrow) * 272 + (msel & 1) * 16 + (wn * 32) * 272;

    float acc[4][4][4] = {};
    asm volatile("cp.async.wait_group 0;" ::: "memory");
    __syncthreads();

#pragma unroll
    for (int ks = 0; ks < 8; ks++) {
        unsigned a[4][4], bf[4][2];
#pragma unroll
        for (int mf = 0; mf < 4; mf++)
            ldm_x4(a[mf][0], a[mf][1], a[mf][2], a[mf][3], aLane + mf * 16 * 272 + ks * 32);
#pragma unroll
        for (int pr = 0; pr < 2; pr++) {
            unsigned t0, t1, t2, t3;
            ldm_x4(t0, t1, t2, t3, bLane + pr * 16 * 272 + ks * 32);
            bf[2 * pr][0] = t0; bf[2 * pr][1] = t1;
            bf[2 * pr + 1][0] = t2; bf[2 * pr + 1][1] = t3;
        }
#pragma unroll
        for (int mf = 0; mf < 4; mf++)
#pragma unroll
            for (int nf = 0; nf < 4; nf++)
                mma_bf16(acc[mf][nf], a[mf], bf[nf]);
    }

#pragma unroll
    for (int mf = 0; mf < 4; mf++) {
        int m = m0 + wm * 64 + mf * 16 + g;
#pragma unroll
        for (int nf = 0; nf < 4; nf++) {
            int cc = c0 + wn * 32 + nf * 8 + 2 * t;
            if (SFUSE) {
                *(unsigned*)&d_Whb[(long)m * HH + cc] = packbf(acc[mf][nf][0], acc[mf][nf][1]);
                *(unsigned*)&d_Whb[(long)(m + 8) * HH + cc] = packbf(acc[mf][nf][2], acc[mf][nf][3]);
            } else {
                float b0 = 0.f, b1 = 0.f;
                if (BIAS) {
                    b0 = bi1[cc] + bi2[cc];
                    b1 = bi1[cc + 1] + bi2[cc + 1];
                }
                *(unsigned*)&d_XGb[(long)m * NTOT + cc] =
                    packbf(acc[mf][nf][0] + b0, acc[mf][nf][1] + b1);
                *(unsigned*)&d_XGb[(long)(m + 8) * NTOT + cc] =
                    packbf(acc[mf][nf][2] + b0, acc[mf][nf][3] + b1);
            }
        }
    }
    if (SFUSE) {
#pragma unroll
        for (int mf = 0; mf < 4; mf++) {
            float ps0 = 0.f, pd0 = 0.f, ps1 = 0.f, pd1 = 0.f;
#pragma unroll
            for (int nf = 0; nf < 4; nf++) {
                int cc = wn * 32 + nf * 8 + 2 * t;
#pragma unroll
                for (int dd = 0; dd < 2; dd++) {
                    float a_s = sA[cc + dd], a_d = sA[128 + cc + dd];
                    ps0 += acc[mf][nf][dd]     * a_s;
                    pd0 += acc[mf][nf][dd]     * a_d;
                    ps1 += acc[mf][nf][2 + dd] * a_s;
                    pd1 += acc[mf][nf][2 + dd] * a_d;
                }
            }
#pragma unroll
            for (int o = 1; o <= 2; o <<= 1) {
                ps0 += __shfl_xor_sync(~0u, ps0, o);
                pd0 += __shfl_xor_sync(~0u, pd0, o);
                ps1 += __shfl_xor_sync(~0u, ps1, o);
                pd1 += __shfl_xor_sync(~0u, pd1, o);
            }
            if (t == 0) {
                int r = wm * 64 + mf * 16 + g;
                red[wn][r][0] = ps0;     red[wn][r][1] = pd0;
                red[wn][r + 8][0] = ps1; red[wn][r + 8][1] = pd1;
            }
        }
        __syncthreads();
        if (tid < 128) {
            float ss = red[0][tid][0] + red[1][tid][0] + red[2][tid][0] + red[3][tid][0];
            float sd = red[0][tid][1] + red[1][tid][1] + red[2][tid][1] + red[3][tid][1];
            long m = m0 + tid;
            d_evb [m] = __float2bfloat16(__expf(sd));
            d_ev2b[m] = __float2bfloat16(__expf(0.2f * sd));
            d_r   [m] = __expf(-0.8f * ss);
        }
    }
}

// ---------------- 3. attention v7: hoisted ev/adj, Wh ring, coalesced epilogue ----
template <int LAYER>
__global__ void __launch_bounds__(256, 2) att_v7_kernel() {
    __shared__ alignas(16) __nv_bfloat16 WhS[3][32][136];   // Wh ring; reused as epi staging [128][72]
    __shared__ alignas(16) __nv_bfloat16 evS [NN];
    __shared__ alignas(16) __nv_bfloat16 ev2S[NN];
    __shared__ alignas(16) unsigned adjS[128 * 33];

    int p = blockIdx.y, row0 = blockIdx.x * 128;
    int tid = threadIdx.x, lane = tid & 31, wid = tid >> 5;
    int b_ = p >> 4;
    int g = lane >> 2, t = lane & 3;

    int rlo = wid * 16 + g;
    float r0f = d_r[p * NN + row0 + rlo];
    float r1f = d_r[p * NN + row0 + rlo + 8];
    unsigned r02 = packbf(r0f, r0f);
    unsigned r12 = packbf(r1f, r1f);

    float acc[16][4] = {};
    float accz[4] = {};
    unsigned bz = (g == 0) ? packbf(1.f, 1.f) : 0u;
    unsigned bz2[2] = {bz, bz};

    const __nv_bfloat16* Whp = &d_Whb[(long)p * NN * HH];
    const unsigned* adjpb = &d_adjp[(long)b_ * NN * (NN / 32)];

    unsigned whbase  = (unsigned)__cvta_generic_to_shared(&WhS[0][0][0]);
    unsigned evbase  = (unsigned)__cvta_generic_to_shared(&evS[0]);
    unsigned ev2base = (unsigned)__cvta_generic_to_shared(&ev2S[0]);
    unsigned laneoff = (lane & 15) * 272 + (lane >> 4) * 16;

    int js = tid >> 4, seg = tid & 15;

    auto STAGE = [&](int i) {
        int bb = i % 3, jc = i * 32;
        const __nv_bfloat16* src = Whp + (long)(jc + js) * HH + seg * 8;
        unsigned dst = whbase + bb * 8704 + js * 272 + seg * 16;
        cpasync16(dst, src);
        cpasync16(dst + 16 * 272, src + 16 * HH);
        cpcommit();
    };

    if (tid < 128) cpasync16(evbase + tid * 16, d_evb + (long)p * NN + tid * 8);
    else           cpasync16(ev2base + (tid - 128) * 16, d_ev2b + (long)p * NN + (tid - 128) * 8);
    {
        const __nv_bfloat16* src = Whp + (long)js * HH + seg * 8;
        unsigned dst = whbase + js * 272 + seg * 16;
        cpasync16(dst, src);
        cpasync16(dst + 16 * 272, src + 16 * HH);
    }
    cpcommit();
    STAGE(1);

    {
        int rr = tid >> 1, half = tid & 1;
        const uint4* src = (const uint4*)(adjpb + (long)(row0 + rr) * 32 + half * 16);
        unsigned* dstw = &adjS[rr * 33 + half * 16];
#pragma unroll
        for (int q = 0; q < 4; q++) {
            uint4 v = src[q];
            dstw[q * 4 + 0] = v.x; dstw[q * 4 + 1] = v.y;
            dstw[q * 4 + 2] = v.z; dstw[q * 4 + 3] = v.w;
        }
    }

    for (int i = 0; i < 32; i++) {
        if (i < 31) { asm volatile("cp.async.wait_group 1;" ::: "memory"); }
        else        { asm volatile("cp.async.wait_group 0;" ::: "memory"); }
        __syncthreads();
        if (i + 2 < 32) STAGE(i + 2);

        int bb = i % 3;
        unsigned awlo = adjS[rlo * 33 + i], awhi = adjS[(rlo + 8) * 33 + i];
        unsigned kb0 = whbase + bb * 8704 + laneoff;
#pragma unroll
        for (int ks = 0; ks < 2; ks++) {
            int jg = i * 32 + ks * 16 + 2 * t;
            int j0 = ks * 16 + 2 * t;
            __nv_bfloat162 evp  = *(__nv_bfloat162*)&evS [jg];
            __nv_bfloat162 evp8 = *(__nv_bfloat162*)&evS [jg + 8];
            __nv_bfloat162 e2p  = *(__nv_bfloat162*)&ev2S[jg];
            __nv_bfloat162 e2p8 = *(__nv_bfloat162*)&ev2S[jg + 8];
            __nv_bfloat162 r0b = *(__nv_bfloat162*)&r02;
            __nv_bfloat162 r1b = *(__nv_bfloat162*)&r12;

            unsigned a[4];
            a[0] = bfu(__hmax2(evp,  __hmul2(r0b, e2p)))  & mask2(awlo, j0);
            a[1] = bfu(__hmax2(evp,  __hmul2(r1b, e2p)))  & mask2(awhi, j0);
            a[2] = bfu(__hmax2(evp8, __hmul2(r0b, e2p8))) & mask2(awlo, j0 + 8);
            a[3] = bfu(__hmax2(evp8, __hmul2(r1b, e2p8))) & mask2(awhi, j0 + 8);

            mma_bf16(accz, a, bz2);

            unsigned kbase = kb0 + ks * 4352;
#pragma unroll
            for (int nc = 0; nc < 8; nc++) {
                unsigned b0, b1, b2, b3;
                ldm_x4_trans(b0, b1, b2, b3, kbase + nc * 32);
                unsigned bf0[2] = {b0, b1}, bf1[2] = {b2, b3};
                mma_bf16(acc[2 * nc], a, bf0);
                mma_bf16(acc[2 * nc + 1], a, bf1);
            }
        }
    }

    float z0 = __shfl_sync(~0u, accz[0], lane & ~3);
    float z1 = __shfl_sync(~0u, accz[2], lane & ~3);
    float iz0 = 1.f / z0, iz1 = 1.f / z1;

    // coalesced epilogue (stride 72 bf16 = 144B, 16B-aligned rows)
    __nv_bfloat16* stg = &WhS[0][0][0];
    __nv_bfloat16* gout = (LAYER == 0) ? d_h1b : d_gb;
#pragma unroll
    for (int half = 0; half < 2; half++) {
        __syncthreads();
#pragma unroll
        for (int nf2 = 0; nf2 < 8; nf2++) {
            int nf = half * 8 + nf2;
            int col = nf2 * 8 + 2 * t;
            *(unsigned*)&stg[rlo * 72 + col]       = packbf(elu2(acc[nf][0] * iz0), elu2(acc[nf][1] * iz0));
            *(unsigned*)&stg[(rlo + 8) * 72 + col] = packbf(elu2(acc[nf][2] * iz1), elu2(acc[nf][3] * iz1));
        }
        __syncthreads();
        int r = tid >> 1, cq = tid & 1;
        const uint4* srow = (const uint4*)&stg[r * 72 + cq * 32];
        uint4* drow = (uint4*)&gout[((long)p * NN + row0 + r) * HH + half * 64 + cq * 32];
#pragma unroll
        for (int q = 0; q < 4; q++) drow[q] = srow[q];
    }
}

// ---------------- 4. LSTM recurrence (bf16 XG) + fused output MLP ----------------
// Hidden-unit lane mapping: element index = 2*lane + u (contiguous bf16x2 loads).
__global__ void lstm_kernel(const float* __restrict__ Whh,
                            const float* __restrict__ Wo1, const float* __restrict__ bo1,
                            const float* __restrict__ Wo2, const float* __restrict__ bo2,
                            float* __restrict__ out) {
    extern __shared__ float sm[];
    float* WT  = sm;                       // [64][257]
    float* hs  = sm + 64 * 257;            // [16][68]
    float* W1s = sm + 64 * 257 + 16 * 68;  // [64][32]
    float* W2s = W1s + 64 * 32;            // [32]
    int tid = threadIdx.x, lane = tid & 31, wp = tid >> 5;
    for (int idx = tid; idx < 256 * 64; idx += 256) {
        int g = idx >> 6, k = idx & 63;
        WT[k * 257 + g] = Whh[g * 64 + k];
    }
    for (int idx = tid; idx < 16 * 68; idx += 256) hs[idx] = 0.f;
    for (int idx = tid; idx < 64 * 32; idx += 256) W1s[idx] = Wo1[idx];
    if (tid < 32) W2s[tid] = Wo2[tid];
    __syncthreads();

    int r0 = wp * 2, r1 = r0 + 1;
    long gr0 = (long)blockIdx.x * 16 + r0;
    long gr1 = gr0 + 1;
    int e0 = 2 * lane, e1 = 2 * lane + 1;   // hidden-unit / gate-sub indices
    float c[2][2] = {};
    float hn[2][2] = {};
    for (int tt = 0; tt < TT; tt++) {
        float acc[2][4][2];
#pragma unroll
        for (int d = 0; d < 2; d++) {
            long base = ((d ? gr1 : gr0) * TT + tt) * 256;
#pragma unroll
            for (int q = 0; q < 4; q++) {
                __nv_bfloat162 v = *(const __nv_bfloat162*)&d_XGb[base + q * 64 + e0];
                acc[d][q][0] = __bfloat162float(v.x);
                acc[d][q][1] = __bfloat162float(v.y);
            }
        }
#pragma unroll 8
        for (int k = 0; k < 64; k++) {
            float h0  = hs[r0 * 68 + k];
            float h1v = hs[r1 * 68 + k];
            const float* wr = &WT[k * 257];
#pragma unroll
            for (int q = 0; q < 4; q++) {
                float wv0 = wr[q * 64 + e0];
                float wv1 = wr[q * 64 + e1];
                acc[0][q][0] += wv0 * h0;  acc[0][q][1] += wv1 * h0;
                acc[1][q][0] += wv0 * h1v; acc[1][q][1] += wv1 * h1v;
            }
        }
#pragma unroll
        for (int d = 0; d < 2; d++)
#pragma unroll
            for (int u = 0; u < 2; u++) {
                float iv = sigf(acc[d][0][u]);
                float fv = sigf(acc[d][1][u]);
                float gv = tanhf_(acc[d][2][u]);
                float ov = sigf(acc[d][3][u]);
                c[d][u]  = fv * c[d][u] + iv * gv;
                hn[d][u] = ov * tanhf_(c[d][u]);
            }
        __syncthreads();
        hs[r0 * 68 + e0] = hn[0][0];
        hs[r0 * 68 + e1] = hn[0][1];
        hs[r1 * 68 + e0] = hn[1][0];
        hs[r1 * 68 + e1] = hn[1][1];
        __syncthreads();
    }

    float b1v = bo1[lane], b2v = bo2[0];
#pragma unroll
    for (int rr = 0; rr < 2; rr++) {
        int r = wp * 2 + rr;
        float a = b1v;
#pragma unroll 16
        for (int k = 0; k < 64; k++) a += hs[r * 68 + k] * W1s[k * 32 + lane];
        float m = fmaxf(a, 0.f) * W2s[lane];
#pragma unroll
        for (int o = 16; o; o >>= 1) m += __shfl_xor_sync(~0u, m, o);
        if (lane == 0) out[(long)blockIdx.x * 16 + r] = m + b2v;
    }
}

// ---------------- launcher ----------------
extern "C" void kernel_launch(void* const* d_in, const int* in_sizes, int n_in,
                              void* d_out, int out_size) {
    const float* x   = (const float*)d_in[0];
    const int*   adj = (const int*)  d_in[1];
    const float* W1  = (const float*)d_in[2];
    const float* a1  = (const float*)d_in[3];
    const float* W2  = (const float*)d_in[4];
    const float* a2  = (const float*)d_in[5];
    const float* Wih = (const float*)d_in[6];
    const float* Whh = (const float*)d_in[7];
    const float* bih = (const float*)d_in[8];
    const float* bhh = (const float*)d_in[9];
    const float* Wo1 = (const float*)d_in[10];
    const float* bo1 = (const float*)d_in[11];
    const float* Wo2 = (const float*)d_in[12];
    const float* bo2 = (const float*)d_in[13];
    float* out = (float*)d_out;

    __nv_bfloat16* d_h1b_p; cudaGetSymbolAddress((void**)&d_h1b_p, d_h1b);
    __nv_bfloat16* d_gb_p;  cudaGetSymbolAddress((void**)&d_gb_p,  d_gb);
    __nv_bfloat16* d_W2b_p; cudaGetSymbolAddress((void**)&d_W2b_p, d_W2b);
    __nv_bfloat16* d_Wihb_p;cudaGetSymbolAddress((void**)&d_Wihb_p,d_Wihb);

    const int L1SM = (4608 + 32 * 136) * sizeof(float);
    const int BFSM = 2 * 128 * 272;
    cudaFuncSetAttribute((const void*)gemm_l1,
                         cudaFuncAttributeMaxDynamicSharedMemorySize, L1SM);
    cudaFuncSetAttribute((const void*)gemm_bf<0, 128, 1, 0>,
                         cudaFuncAttributeMaxDynamicSharedMemorySize, BFSM);
    cudaFuncSetAttribute((const void*)gemm_bf<1, 256, 0, 1>,
                         cudaFuncAttributeMaxDynamicSharedMemorySize, BFSM);

    prep_all<<<512, 256>>>(adj, W2, Wih);

    // GAT layer 1
    gemm_l1<<<512, 256, L1SM>>>(x, W1, a1);
    att_v7_kernel<0><<<dim3(8, 64), 256>>>();

    // GAT layer 2 (bf16 GEMM)
    gemm_bf<0, 128, 1, 0><<<dim3(512, 1), 256, BFSM>>>(d_h1b_p, d_W2b_p, nullptr, nullptr, a2);

    att_v7_kernel<1><<<dim3(8, 64), 256>>>();

    // LSTM input gates (gathers d_gb [p][n][h], writes bf16 XG)
    gemm_bf<1, 256, 0, 1><<<dim3(512, 2), 256, BFSM>>>(d_gb_p, d_Wihb_p, bih, bhh, nullptr);

    // LSTM recurrence + fused MLP
    size_t smem = (64 * 257 + 16 * 68 + 64 * 32 + 32) * sizeof(float);
    cudaFuncSetAttribute(lstm_kernel, cudaFuncAttributeMaxDynamicSharedMemorySize, (int)smem);
    lstm_kernel<<<256, 256, smem>>>(Whh, Wo1, bo1, Wo2, bo2, out);
}

// round 15
// speedup vs baseline: 1.0523x; 1.0523x over previous
#include <cuda_runtime.h>
#include <cuda_bf16.h>
#include <cstdint>

#define BB   4
#define NN   1024
#define TT   16
#define FINN 32
#define HH   128
#define LHID 64
#define NP   64
#define MTOT (NP * NN)

// ---------------- scratch ----------------
__device__ __nv_bfloat16 d_Whb[MTOT * HH];        // bf16 Wh (GEMM epilogue output, row-major)
__device__ __nv_bfloat16 d_h1b[MTOT * HH];        // bf16 layer-1 output [p][n][h]
__device__ __nv_bfloat16 d_gb [MTOT * HH];        // bf16 layer-2 output [p][n][h]
__device__ __nv_bfloat16 d_evb [MTOT];
__device__ __nv_bfloat16 d_ev2b[MTOT];
__device__ float         d_r  [MTOT];             // e^{-0.8 s_src}
__device__ unsigned      d_adjp[BB * NN * (NN / 32)];
__device__ __nv_bfloat16 d_XGb[MTOT * 256];       // bf16 input gates (bias included)
__device__ __nv_bfloat16 d_W2b [HH * HH];         // W2 transposed -> [n][k] bf16
__device__ __nv_bfloat16 d_Wihb[256 * HH];        // Wih [gate][k] bf16

// ---------------- helpers ----------------
__device__ __forceinline__ float sigf(float x)   { return 1.f / (1.f + __expf(-x)); }
__device__ __forceinline__ float tanhf_(float x) { return 1.f - 2.f / (__expf(2.f * x) + 1.f); }
__device__ __forceinline__ void mma_tf32(float* c, const unsigned* a, const unsigned* b) {
    asm volatile("mma.sync.aligned.m16n8k8.row.col.f32.tf32.tf32.f32 "
                 "{%0,%1,%2,%3}, {%4,%5,%6,%7}, {%8,%9}, {%0,%1,%2,%3};"
                 : "+f"(c[0]), "+f"(c[1]), "+f"(c[2]), "+f"(c[3])
                 : "r"(a[0]), "r"(a[1]), "r"(a[2]), "r"(a[3]), "r"(b[0]), "r"(b[1]));
}
__device__ __forceinline__ void mma_bf16(float* c, const unsigned* a, const unsigned* b) {
    asm volatile("mma.sync.aligned.m16n8k16.row.col.f32.bf16.bf16.f32 "
                 "{%0,%1,%2,%3}, {%4,%5,%6,%7}, {%8,%9}, {%0,%1,%2,%3};"
                 : "+f"(c[0]), "+f"(c[1]), "+f"(c[2]), "+f"(c[3])
                 : "r"(a[0]), "r"(a[1]), "r"(a[2]), "r"(a[3]), "r"(b[0]), "r"(b[1]));
}
__device__ __forceinline__ void ldm_x4(unsigned& r0, unsigned& r1, unsigned& r2, unsigned& r3,
                                       unsigned saddr) {
    asm volatile("ldmatrix.sync.aligned.m8n8.x4.shared.b16 {%0,%1,%2,%3}, [%4];"
                 : "=r"(r0), "=r"(r1), "=r"(r2), "=r"(r3) : "r"(saddr));
}
__device__ __forceinline__ void ldm_x4_trans(unsigned& r0, unsigned& r1, unsigned& r2, unsigned& r3,
                                             unsigned saddr) {
    asm volatile("ldmatrix.sync.aligned.m8n8.x4.trans.shared.b16 {%0,%1,%2,%3}, [%4];"
                 : "=r"(r0), "=r"(r1), "=r"(r2), "=r"(r3) : "r"(saddr));
}
__device__ __forceinline__ void cpasync16(unsigned saddr, const void* g) {
    asm volatile("cp.async.ca.shared.global [%0], [%1], 16;" :: "r"(saddr), "l"(g));
}
__device__ __forceinline__ void cpcommit() { asm volatile("cp.async.commit_group;"); }
__device__ __forceinline__ float elu2(float v) {
    v = v > 0.f ? v : __expf(v) - 1.f;
    v = v > 0.f ? v : __expf(v) - 1.f;
    return v;
}
__device__ __forceinline__ unsigned packbf(float a, float b) {
    __nv_bfloat162 p = __floats2bfloat162_rn(a, b);
    return *(unsigned*)&p;
}
__device__ __forceinline__ unsigned bfu(__nv_bfloat162 v) { return *(unsigned*)&v; }
__device__ __forceinline__ unsigned mask2(unsigned aw, int j0) {
    unsigned m = 0;
    if ((aw >> j0) & 1u)       m |= 0x0000FFFFu;
    if ((aw >> (j0 + 1)) & 1u) m |= 0xFFFF0000u;
    return m;
}

// ---------------- 1. prep: pack adjacency + bf16 weights (one launch) ----------------
__global__ void prep_all(const int* __restrict__ adj,
                         const float* __restrict__ W2, const float* __restrict__ Wih) {
    int idx = blockIdx.x * blockDim.x + threadIdx.x;
    if (idx < BB * NN * (NN / 32)) {
        long base = (long)idx * 32;
        unsigned bits = 0;
#pragma unroll
        for (int j = 0; j < 32; j++) bits |= (adj[base + j] > 0 ? 1u : 0u) << j;
        d_adjp[idx] = bits;
    }
    if (idx < HH * HH) {
        int n = idx >> 7, k = idx & 127;
        d_W2b[idx] = __float2bfloat16(W2[k * HH + n]);
    }
    if (idx < 256 * HH)
        d_Wihb[idx] = __float2bfloat16(Wih[idx]);
}

// ---------------- 2a. tf32 GEMM (layer 1: x gathered, K=32) -> d_Whb + scores ----
__global__ void __launch_bounds__(256, 2) gemm_l1(const float* __restrict__ A,
                                                  const float* __restrict__ Bw,
                                                  const float* __restrict__ avec) {
    int m0 = blockIdx.x * 128;
    int tid = threadIdx.x, lane = tid & 31, wid = tid >> 5;
    int wm = wid >> 2, wn = wid & 3;
    int g = lane >> 2, t = lane & 3;

    extern __shared__ float gsm[];
    float* As = gsm;             // [128][36]
    float* Bs = gsm + 4608;      // [32][136]
    __shared__ float sA[256];
    __shared__ float red[4][128][2];

    sA[tid] = avec[tid];

    float acc[4][4][4] = {};
    {
        int r = tid >> 1, k0 = (tid & 1) * 16;
        int m = m0 + r;
        int n = m & (NN - 1);
        int pp = m >> 10, tt2 = pp & 15, bb2 = pp >> 4;
        long base = (((long)(bb2 * NN + n) * TT + tt2) * FINN) + k0;
        unsigned dst = (unsigned)__cvta_generic_to_shared(&As[r * 36 + k0]);
#pragma unroll
        for (int q = 0; q < 4; q++) cpasync16(dst + q * 16, A + base + q * 4);
    }
    {
        int kr = tid >> 3, cq = tid & 7;
        const float* src = Bw + (long)kr * HH + cq * 16;
        unsigned dst = (unsigned)__cvta_generic_to_shared(&Bs[kr * 136 + cq * 16]);
#pragma unroll
        for (int q = 0; q < 4; q++) cpasync16(dst + q * 16, src + q * 4);
    }
    cpcommit();
    asm volatile("cp.async.wait_group 0;" ::: "memory");
    __syncthreads();

#pragma unroll
    for (int ks = 0; ks < 4; ks++) {
        unsigned a[4][4], bf[4][2];
#pragma unroll
        for (int mf = 0; mf < 4; mf++) {
            int r = wm * 64 + mf * 16 + g;
            a[mf][0] = __float_as_uint(As[r * 36 + ks * 8 + t]);
            a[mf][1] = __float_as_uint(As[(r + 8) * 36 + ks * 8 + t]);
            a[mf][2] = __float_as_uint(As[r * 36 + ks * 8 + t + 4]);
            a[mf][3] = __float_as_uint(As[(r + 8) * 36 + ks * 8 + t + 4]);
        }
#pragma unroll
        for (int nf = 0; nf < 4; nf++) {
            int cc = wn * 32 + nf * 8 + g;
            bf[nf][0] = __float_as_uint(Bs[(ks * 8 + t) * 136 + cc]);
            bf[nf][1] = __float_as_uint(Bs[(ks * 8 + t + 4) * 136 + cc]);
        }
#pragma unroll
        for (int mf = 0; mf < 4; mf++)
#pragma unroll
            for (int nf = 0; nf < 4; nf++)
                mma_tf32(acc[mf][nf], a[mf], bf[nf]);
    }

    // store bf16 Wh + fused scores
#pragma unroll
    for (int mf = 0; mf < 4; mf++) {
        int r = m0 + wm * 64 + mf * 16 + g;
#pragma unroll
        for (int nf = 0; nf < 4; nf++) {
            int cc = wn * 32 + nf * 8 + 2 * t;
            *(unsigned*)&d_Whb[(long)r * HH + cc] = packbf(acc[mf][nf][0], acc[mf][nf][1]);
            *(unsigned*)&d_Whb[(long)(r + 8) * HH + cc] = packbf(acc[mf][nf][2], acc[mf][nf][3]);
        }
    }
#pragma unroll
    for (int mf = 0; mf < 4; mf++) {
        float ps0 = 0.f, pd0 = 0.f, ps1 = 0.f, pd1 = 0.f;
#pragma unroll
        for (int nf = 0; nf < 4; nf++) {
            int cc = wn * 32 + nf * 8 + 2 * t;
#pragma unroll
            for (int dd = 0; dd < 2; dd++) {
                float a_s = sA[cc + dd], a_d = sA[128 + cc + dd];
                ps0 += acc[mf][nf][dd]     * a_s;
                pd0 += acc[mf][nf][dd]     * a_d;
                ps1 += acc[mf][nf][2 + dd] * a_s;
                pd1 += acc[mf][nf][2 + dd] * a_d;
            }
        }
#pragma unroll
        for (int o = 1; o <= 2; o <<= 1) {
            ps0 += __shfl_xor_sync(~0u, ps0, o);
            pd0 += __shfl_xor_sync(~0u, pd0, o);
            ps1 += __shfl_xor_sync(~0u, ps1, o);
            pd1 += __shfl_xor_sync(~0u, pd1, o);
        }
        if (t == 0) {
            int r = wm * 64 + mf * 16 + g;
            red[wn][r][0] = ps0;     red[wn][r][1] = pd0;
            red[wn][r + 8][0] = ps1; red[wn][r + 8][1] = pd1;
        }
    }
    __syncthreads();
    if (tid < 128) {
        float ss = red[0][tid][0] + red[1][tid][0] + red[2][tid][0] + red[3][tid][0];
        float sd = red[0][tid][1] + red[1][tid][1] + red[2][tid][1] + red[3][tid][1];
        long m = m0 + tid;
        d_evb [m] = __float2bfloat16(__expf(sd));
        d_ev2b[m] = __float2bfloat16(__expf(0.2f * sd));
        d_r   [m] = __expf(-0.8f * ss);
    }
}

// ---------------- 2b. bf16 GEMM (K=128) ----------------
template <int BIAS, int NTOT, int SFUSE, int AMODE>
__global__ void __launch_bounds__(256, 2) gemm_bf(const __nv_bfloat16* __restrict__ A,
                                                  const __nv_bfloat16* __restrict__ Bw,
                                                  const float* __restrict__ bi1,
                                                  const float* __restrict__ bi2,
                                                  const float* __restrict__ avec) {
    int m0 = blockIdx.x * 128;
    int c0 = blockIdx.y * 128;
    int tid = threadIdx.x, lane = tid & 31, wid = tid >> 5;
    int wm = wid >> 2, wn = wid & 3;
    int g = lane >> 2, t = lane & 3;

    extern __shared__ __nv_bfloat16 bsm[];
    unsigned asmem = (unsigned)__cvta_generic_to_shared(&bsm[0]);
    unsigned bsmem = asmem + 128 * 272;
    __shared__ float sA[SFUSE ? 256 : 1];
    __shared__ float red[SFUSE ? 4 : 1][SFUSE ? 128 : 1][2];

    if (SFUSE) sA[tid] = avec[tid];

    {
        int r = tid >> 1, h = (tid & 1) * 8;
        long arow;
        if (AMODE == 0) {
            arow = (long)(m0 + r) * HH;
        } else {
            int m = m0 + r;
            int tt2 = m & 15, bn = m >> 4;
            int n = bn & (NN - 1), b = bn >> 10;
            arow = ((long)(b * TT + tt2) * NN + n) * HH;
        }
        const __nv_bfloat16* asrc = A + arow + h * 8;
        const __nv_bfloat16* bsrc = Bw + (long)(c0 + r) * HH + h * 8;
        unsigned adst = asmem + r * 272 + h * 16;
        unsigned bdst = bsmem + r * 272 + h * 16;
#pragma unroll
        for (int q = 0; q < 8; q++) {
            cpasync16(adst + q * 16, asrc + q * 8);
            cpasync16(bdst + q * 16, bsrc + q * 8);
        }
    }
    cpcommit();

    int mrow = lane & 7, msel = lane >> 3;
    unsigned aLane = asmem + ((msel & 1) * 8 + mrow) * 272 + (msel >> 1) * 16 + (wm * 64) * 272;
    unsigned bLane = bsmem + ((msel >> 1) * 8 + mrow) * 272 + (msel & 1) * 16 + (wn * 32) * 272;

    float acc[4][4][4] = {};
    asm volatile("cp.async.wait_group 0;" ::: "memory");
    __syncthreads();

#pragma unroll
    for (int ks = 0; ks < 8; ks++) {
        unsigned a[4][4], bf[4][2];
#pragma unroll
        for (int mf = 0; mf < 4; mf++)
            ldm_x4(a[mf][0], a[mf][1], a[mf][2], a[mf][3], aLane + mf * 16 * 272 + ks * 32);
#pragma unroll
        for (int pr = 0; pr < 2; pr++) {
            unsigned t0, t1, t2, t3;
            ldm_x4(t0, t1, t2, t3, bLane + pr * 16 * 272 + ks * 32);
            bf[2 * pr][0] = t0; bf[2 * pr][1] = t1;
            bf[2 * pr + 1][0] = t2; bf[2 * pr + 1][1] = t3;
        }
#pragma unroll
        for (int mf = 0; mf < 4; mf++)
#pragma unroll
            for (int nf = 0; nf < 4; nf++)
                mma_bf16(acc[mf][nf], a[mf], bf[nf]);
    }

#pragma unroll
    for (int mf = 0; mf < 4; mf++) {
        int m = m0 + wm * 64 + mf * 16 + g;
#pragma unroll
        for (int nf = 0; nf < 4; nf++) {
            int cc = c0 + wn * 32 + nf * 8 + 2 * t;
            if (SFUSE) {
                *(unsigned*)&d_Whb[(long)m * HH + cc] = packbf(acc[mf][nf][0], acc[mf][nf][1]);
                *(unsigned*)&d_Whb[(long)(m + 8) * HH + cc] = packbf(acc[mf][nf][2], acc[mf][nf][3]);
            } else {
                float b0 = 0.f, b1 = 0.f;
                if (BIAS) {
                    b0 = bi1[cc] + bi2[cc];
                    b1 = bi1[cc + 1] + bi2[cc + 1];
                }
                *(unsigned*)&d_XGb[(long)m * NTOT + cc] =
                    packbf(acc[mf][nf][0] + b0, acc[mf][nf][1] + b1);
                *(unsigned*)&d_XGb[(long)(m + 8) * NTOT + cc] =
                    packbf(acc[mf][nf][2] + b0, acc[mf][nf][3] + b1);
            }
        }
    }
    if (SFUSE) {
#pragma unroll
        for (int mf = 0; mf < 4; mf++) {
            float ps0 = 0.f, pd0 = 0.f, ps1 = 0.f, pd1 = 0.f;
#pragma unroll
            for (int nf = 0; nf < 4; nf++) {
                int cc = wn * 32 + nf * 8 + 2 * t;
#pragma unroll
                for (int dd = 0; dd < 2; dd++) {
                    float a_s = sA[cc + dd], a_d = sA[128 + cc + dd];
                    ps0 += acc[mf][nf][dd]     * a_s;
                    pd0 += acc[mf][nf][dd]     * a_d;
                    ps1 += acc[mf][nf][2 + dd] * a_s;
                    pd1 += acc[mf][nf][2 + dd] * a_d;
                }
            }
#pragma unroll
            for (int o = 1; o <= 2; o <<= 1) {
                ps0 += __shfl_xor_sync(~0u, ps0, o);
                pd0 += __shfl_xor_sync(~0u, pd0, o);
                ps1 += __shfl_xor_sync(~0u, ps1, o);
                pd1 += __shfl_xor_sync(~0u, pd1, o);
            }
            if (t == 0) {
                int r = wm * 64 + mf * 16 + g;
                red[wn][r][0] = ps0;     red[wn][r][1] = pd0;
                red[wn][r + 8][0] = ps1; red[wn][r + 8][1] = pd1;
            }
        }
        __syncthreads();
        if (tid < 128) {
            float ss = red[0][tid][0] + red[1][tid][0] + red[2][tid][0] + red[3][tid][0];
            float sd = red[0][tid][1] + red[1][tid][1] + red[2][tid][1] + red[3][tid][1];
            long m = m0 + tid;
            d_evb [m] = __float2bfloat16(__expf(sd));
            d_ev2b[m] = __float2bfloat16(__expf(0.2f * sd));
            d_r   [m] = __expf(-0.8f * ss);
        }
    }
}

// ---------------- 3. attention v7 ----------------
template <int LAYER>
__global__ void __launch_bounds__(256, 2) att_v7_kernel() {
    __shared__ alignas(16) __nv_bfloat16 WhS[3][32][136];
    __shared__ alignas(16) __nv_bfloat16 evS [NN];
    __shared__ alignas(16) __nv_bfloat16 ev2S[NN];
    __shared__ alignas(16) unsigned adjS[128 * 33];

    int p = blockIdx.y, row0 = blockIdx.x * 128;
    int tid = threadIdx.x, lane = tid & 31, wid = tid >> 5;
    int b_ = p >> 4;
    int g = lane >> 2, t = lane & 3;

    int rlo = wid * 16 + g;
    float r0f = d_r[p * NN + row0 + rlo];
    float r1f = d_r[p * NN + row0 + rlo + 8];
    unsigned r02 = packbf(r0f, r0f);
    unsigned r12 = packbf(r1f, r1f);

    float acc[16][4] = {};
    float accz[4] = {};
    unsigned bz = (g == 0) ? packbf(1.f, 1.f) : 0u;
    unsigned bz2[2] = {bz, bz};

    const __nv_bfloat16* Whp = &d_Whb[(long)p * NN * HH];
    const unsigned* adjpb = &d_adjp[(long)b_ * NN * (NN / 32)];

    unsigned whbase  = (unsigned)__cvta_generic_to_shared(&WhS[0][0][0]);
    unsigned evbase  = (unsigned)__cvta_generic_to_shared(&evS[0]);
    unsigned ev2base = (unsigned)__cvta_generic_to_shared(&ev2S[0]);
    unsigned laneoff = (lane & 15) * 272 + (lane >> 4) * 16;

    int js = tid >> 4, seg = tid & 15;

    auto STAGE = [&](int i) {
        int bb = i % 3, jc = i * 32;
        const __nv_bfloat16* src = Whp + (long)(jc + js) * HH + seg * 8;
        unsigned dst = whbase + bb * 8704 + js * 272 + seg * 16;
        cpasync16(dst, src);
        cpasync16(dst + 16 * 272, src + 16 * HH);
        cpcommit();
    };

    if (tid < 128) cpasync16(evbase + tid * 16, d_evb + (long)p * NN + tid * 8);
    else           cpasync16(ev2base + (tid - 128) * 16, d_ev2b + (long)p * NN + (tid - 128) * 8);
    {
        const __nv_bfloat16* src = Whp + (long)js * HH + seg * 8;
        unsigned dst = whbase + js * 272 + seg * 16;
        cpasync16(dst, src);
        cpasync16(dst + 16 * 272, src + 16 * HH);
    }
    cpcommit();
    STAGE(1);

    {
        int rr = tid >> 1, half = tid & 1;
        const uint4* src = (const uint4*)(adjpb + (long)(row0 + rr) * 32 + half * 16);
        unsigned* dstw = &adjS[rr * 33 + half * 16];
#pragma unroll
        for (int q = 0; q < 4; q++) {
            uint4 v = src[q];
            dstw[q * 4 + 0] = v.x; dstw[q * 4 + 1] = v.y;
            dstw[q * 4 + 2] = v.z; dstw[q * 4 + 3] = v.w;
        }
    }

    for (int i = 0; i < 32; i++) {
        if (i < 31) { asm volatile("cp.async.wait_group 1;" ::: "memory"); }
        else        { asm volatile("cp.async.wait_group 0;" ::: "memory"); }
        __syncthreads();
        if (i + 2 < 32) STAGE(i + 2);

        int bb = i % 3;
        unsigned awlo = adjS[rlo * 33 + i], awhi = adjS[(rlo + 8) * 33 + i];
        unsigned kb0 = whbase + bb * 8704 + laneoff;
#pragma unroll
        for (int ks = 0; ks < 2; ks++) {
            int jg = i * 32 + ks * 16 + 2 * t;
            int j0 = ks * 16 + 2 * t;
            __nv_bfloat162 evp  = *(__nv_bfloat162*)&evS [jg];
            __nv_bfloat162 evp8 = *(__nv_bfloat162*)&evS [jg + 8];
            __nv_bfloat162 e2p  = *(__nv_bfloat162*)&ev2S[jg];
            __nv_bfloat162 e2p8 = *(__nv_bfloat162*)&ev2S[jg + 8];
            __nv_bfloat162 r0b = *(__nv_bfloat162*)&r02;
            __nv_bfloat162 r1b = *(__nv_bfloat162*)&r12;

            unsigned a[4];
            a[0] = bfu(__hmax2(evp,  __hmul2(r0b, e2p)))  & mask2(awlo, j0);
            a[1] = bfu(__hmax2(evp,  __hmul2(r1b, e2p)))  & mask2(awhi, j0);
            a[2] = bfu(__hmax2(evp8, __hmul2(r0b, e2p8))) & mask2(awlo, j0 + 8);
            a[3] = bfu(__hmax2(evp8, __hmul2(r1b, e2p8))) & mask2(awhi, j0 + 8);

            mma_bf16(accz, a, bz2);

            unsigned kbase = kb0 + ks * 4352;
#pragma unroll
            for (int nc = 0; nc < 8; nc++) {
                unsigned b0, b1, b2, b3;
                ldm_x4_trans(b0, b1, b2, b3, kbase + nc * 32);
                unsigned bf0[2] = {b0, b1}, bf1[2] = {b2, b3};
                mma_bf16(acc[2 * nc], a, bf0);
                mma_bf16(acc[2 * nc + 1], a, bf1);
            }
        }
    }

    float z0 = __shfl_sync(~0u, accz[0], lane & ~3);
    float z1 = __shfl_sync(~0u, accz[2], lane & ~3);
    float iz0 = 1.f / z0, iz1 = 1.f / z1;

    __nv_bfloat16* stg = &WhS[0][0][0];
    __nv_bfloat16* gout = (LAYER == 0) ? d_h1b : d_gb;
#pragma unroll
    for (int half = 0; half < 2; half++) {
        __syncthreads();
#pragma unroll
        for (int nf2 = 0; nf2 < 8; nf2++) {
            int nf = half * 8 + nf2;
            int col = nf2 * 8 + 2 * t;
            *(unsigned*)&stg[rlo * 72 + col]       = packbf(elu2(acc[nf][0] * iz0), elu2(acc[nf][1] * iz0));
            *(unsigned*)&stg[(rlo + 8) * 72 + col] = packbf(elu2(acc[nf][2] * iz1), elu2(acc[nf][3] * iz1));
        }
        __syncthreads();
        int r = tid >> 1, cq = tid & 1;
        const uint4* srow = (const uint4*)&stg[r * 72 + cq * 32];
        uint4* drow = (uint4*)&gout[((long)p * NN + row0 + r) * HH + half * 64 + cq * 32];
#pragma unroll
        for (int q = 0; q < 4; q++) drow[q] = srow[q];
    }
}

// ---------------- 4. LSTM recurrence (bf16 XG, conflict-free lane map) + MLP ----------
__global__ void lstm_kernel(const float* __restrict__ Whh,
                            const float* __restrict__ Wo1, const float* __restrict__ bo1,
                            const float* __restrict__ Wo2, const float* __restrict__ bo2,
                            float* __restrict__ out) {
    extern __shared__ float sm[];
    float* WT  = sm;                       // [64][257]
    float* hs  = sm + 64 * 257;            // [16][68]
    float* W1s = sm + 64 * 257 + 16 * 68;  // [64][32]
    float* W2s = W1s + 64 * 32;            // [32]
    int tid = threadIdx.x, lane = tid & 31, wp = tid >> 5;
    for (int idx = tid; idx < 256 * 64; idx += 256) {
        int g = idx >> 6, k = idx & 63;
        WT[k * 257 + g] = Whh[g * 64 + k];
    }
    for (int idx = tid; idx < 16 * 68; idx += 256) hs[idx] = 0.f;
    for (int idx = tid; idx < 64 * 32; idx += 256) W1s[idx] = Wo1[idx];
    if (tid < 32) W2s[tid] = Wo2[tid];
    __syncthreads();

    int r0 = wp * 2, r1 = r0 + 1;
    long gr0 = (long)blockIdx.x * 16 + r0;
    long gr1 = gr0 + 1;
    float c[2][2] = {};
    float hn[2][2] = {};
    for (int tt = 0; tt < TT; tt++) {
        float acc[2][4][2];
#pragma unroll
        for (int d = 0; d < 2; d++) {
            long base = ((d ? gr1 : gr0) * TT + tt) * 256;
#pragma unroll
            for (int q = 0; q < 4; q++) {
                acc[d][q][0] = __bfloat162float(d_XGb[base + q * 64 + lane]);
                acc[d][q][1] = __bfloat162float(d_XGb[base + q * 64 + 32 + lane]);
            }
        }
#pragma unroll 8
        for (int k = 0; k < 64; k++) {
            float h0  = hs[r0 * 68 + k];
            float h1v = hs[r1 * 68 + k];
            const float* wr = &WT[k * 257];
#pragma unroll
            for (int q = 0; q < 4; q++) {
                float wv0 = wr[q * 64 + lane];
                float wv1 = wr[q * 64 + 32 + lane];
                acc[0][q][0] += wv0 * h0;  acc[0][q][1] += wv1 * h0;
                acc[1][q][0] += wv0 * h1v; acc[1][q][1] += wv1 * h1v;
            }
        }
#pragma unroll
        for (int d = 0; d < 2; d++)
#pragma unroll
            for (int u = 0; u < 2; u++) {
                float iv = sigf(acc[d][0][u]);
                float fv = sigf(acc[d][1][u]);
                float gv = tanhf_(acc[d][2][u]);
                float ov = sigf(acc[d][3][u]);
                c[d][u]  = fv * c[d][u] + iv * gv;
                hn[d][u] = ov * tanhf_(c[d][u]);
            }
        __syncthreads();
        hs[r0 * 68 + lane]      = hn[0][0];
        hs[r0 * 68 + 32 + lane] = hn[0][1];
        hs[r1 * 68 + lane]      = hn[1][0];
        hs[r1 * 68 + 32 + lane] = hn[1][1];
        __syncthreads();
    }

    float b1v = bo1[lane], b2v = bo2[0];
#pragma unroll
    for (int rr = 0; rr < 2; rr++) {
        int r = wp * 2 + rr;
        float a = b1v;
#pragma unroll 16
        for (int k = 0; k < 64; k++) a += hs[r * 68 + k] * W1s[k * 32 + lane];
        float m = fmaxf(a, 0.f) * W2s[lane];
#pragma unroll
        for (int o = 16; o; o >>= 1) m += __shfl_xor_sync(~0u, m, o);
        if (lane == 0) out[(long)blockIdx.x * 16 + r] = m + b2v;
    }
}

// ---------------- launcher ----------------
extern "C" void kernel_launch(void* const* d_in, const int* in_sizes, int n_in,
                              void* d_out, int out_size) {
    const float* x   = (const float*)d_in[0];
    const int*   adj = (const int*)  d_in[1];
    const float* W1  = (const float*)d_in[2];
    const float* a1  = (const float*)d_in[3];
    const float* W2  = (const float*)d_in[4];
    const float* a2  = (const float*)d_in[5];
    const float* Wih = (const float*)d_in[6];
    const float* Whh = (const float*)d_in[7];
    const float* bih = (const float*)d_in[8];
    const float* bhh = (const float*)d_in[9];
    const float* Wo1 = (const float*)d_in[10];
    const float* bo1 = (const float*)d_in[11];
    const float* Wo2 = (const float*)d_in[12];
    const float* bo2 = (const float*)d_in[13];
    float* out = (float*)d_out;

    __nv_bfloat16* d_h1b_p; cudaGetSymbolAddress((void**)&d_h1b_p, d_h1b);
    __nv_bfloat16* d_gb_p;  cudaGetSymbolAddress((void**)&d_gb_p,  d_gb);
    __nv_bfloat16* d_W2b_p; cudaGetSymbolAddress((void**)&d_W2b_p, d_W2b);
    __nv_bfloat16* d_Wihb_p;cudaGetSymbolAddress((void**)&d_Wihb_p,d_Wihb);

    const int L1SM = (4608 + 32 * 136) * sizeof(float);
    const int BFSM = 2 * 128 * 272;
    cudaFuncSetAttribute((const void*)gemm_l1,
                         cudaFuncAttributeMaxDynamicSharedMemorySize, L1SM);
    cudaFuncSetAttribute((const void*)gemm_bf<0, 128, 1, 0>,
                         cudaFuncAttributeMaxDynamicSharedMemorySize, BFSM);
    cudaFuncSetAttribute((const void*)gemm_bf<1, 256, 0, 1>,
                         cudaFuncAttributeMaxDynamicSharedMemorySize, BFSM);

    prep_all<<<512, 256>>>(adj, W2, Wih);

    // GAT layer 1
    gemm_l1<<<512, 256, L1SM>>>(x, W1, a1);
    att_v7_kernel<0><<<dim3(8, 64), 256>>>();

    // GAT layer 2 (bf16 GEMM)
    gemm_bf<0, 128, 1, 0><<<dim3(512, 1), 256, BFSM>>>(d_h1b_p, d_W2b_p, nullptr, nullptr, a2);

    att_v7_kernel<1><<<dim3(8, 64), 256>>>();

    // LSTM input gates (gathers d_gb [p][n][h], writes bf16 XG)
    gemm_bf<1, 256, 0, 1><<<dim3(512, 2), 256, BFSM>>>(d_gb_p, d_Wihb_p, bih, bhh, nullptr);

    // LSTM recurrence + fused MLP
    size_t smem = (64 * 257 + 16 * 68 + 64 * 32 + 32) * sizeof(float);
    cudaFuncSetAttribute(lstm_kernel, cudaFuncAttributeMaxDynamicSharedMemorySize, (int)smem);
    lstm_kernel<<<256, 256, smem>>>(Whh, Wo1, bo1, Wo2, bo2, out);
}